// round 1
// baseline (speedup 1.0000x reference)
#include <cuda_runtime.h>
#include <math.h>

#define B_   32
#define CIN  256
#define COUT 512
#define A_   256
#define HW   4096

// ---- scratch (no allocations allowed) ----
__device__ float d_WxT[CIN * A_];     // Wx transposed: [c][a]
__device__ float d_gg[B_ * A_];       // g @ Wg^T + bg
__device__ float d_attraw[B_ * HW];   // pre-normalization attention scores
__device__ float d_bmin[B_];
__device__ float d_bsum[B_];

// ---------------- K0: transpose Wx[a][c] -> WxT[c][a] ----------------
__global__ void k_transpose(const float* __restrict__ Wx) {
    __shared__ float t[32][33];
    int tx = threadIdx.x, ty = threadIdx.y;
    int c = blockIdx.x * 32 + tx;          // contiguous dim of Wx
    int a0 = blockIdx.y * 32;
    #pragma unroll
    for (int i = 0; i < 32; i += 8)
        t[ty + i][tx] = Wx[(size_t)(a0 + ty + i) * CIN + c];
    __syncthreads();
    int cw = blockIdx.x * 32 + ty;         // row of WxT
    int aw = a0 + tx;                      // contiguous dim of WxT
    #pragma unroll
    for (int i = 0; i < 32; i += 8)
        d_WxT[(size_t)(cw + i) * A_ + aw] = t[tx][ty + i];
}

// ---------------- K1: gg[b][a] = sum_k g[b][k]*Wg[a][k] + bg[a] ------
__global__ void k_gg(const float* __restrict__ g,
                     const float* __restrict__ Wg,
                     const float* __restrict__ bg) {
    __shared__ float gs[COUT];
    int b = blockIdx.x, tid = threadIdx.x;
    gs[tid]       = g[b * COUT + tid];
    gs[tid + 256] = g[b * COUT + tid + 256];
    __syncthreads();
    int warp = tid >> 5, lane = tid & 31;
    for (int a = warp; a < A_; a += 8) {
        float s = 0.f;
        for (int k = lane; k < COUT; k += 32)
            s += gs[k] * Wg[(size_t)a * COUT + k];
        #pragma unroll
        for (int o = 16; o; o >>= 1) s += __shfl_down_sync(0xffffffffu, s, o);
        if (!lane) d_gg[b * A_ + a] = s + bg[a];
    }
}

// ---------------- K2: fused GEMM + relu + Wf dot ---------------------
// Per block: batch b, 64 spatial positions. Computes
//   attraw[b][n] = sum_a relu(gg[b][a]+bx[a] + sum_c x[b][c][n]*Wx[a][c]) * Wf[a] + bf
__global__ __launch_bounds__(256, 2) void k_main(
        const float* __restrict__ x,
        const float* __restrict__ bx,
        const float* __restrict__ Wf,
        const float* __restrict__ bf) {
    __shared__ float s_x[2112];       // xs[32][64] main loop; red[64][33] epilogue
    __shared__ float s_w[32 * 256];   // WxT chunk [kc][a]
    __shared__ float s_gb[256];
    __shared__ float s_wf[256];

    int b = blockIdx.y, n0 = blockIdx.x * 64;
    int tid = threadIdx.x;
    int tx = tid & 7;     // n sub-tile (8 n's)
    int ty = tid >> 3;    // a sub-tile (8 a's), 32 groups

    s_gb[tid] = d_gg[b * A_ + tid] + bx[tid];
    s_wf[tid] = Wf[tid];

    float acc[8][8];
    #pragma unroll
    for (int i = 0; i < 8; i++)
        #pragma unroll
        for (int j = 0; j < 8; j++) acc[i][j] = 0.f;

    const float* xb = x + (size_t)b * CIN * HW + n0;

    for (int c0 = 0; c0 < CIN; c0 += 32) {
        __syncthreads();
        // xs: 32 c-rows x 64 n (2048 floats)
        #pragma unroll
        for (int t = 0; t < 8; t++) {
            int idx = tid + t * 256;
            int kc = idx >> 6, n = idx & 63;
            s_x[idx] = xb[(size_t)(c0 + kc) * HW + n];
        }
        // ws: 32 c-rows x 256 a (8192 floats), fully coalesced from WxT
        #pragma unroll
        for (int t = 0; t < 32; t++) {
            int idx = tid + t * 256;
            s_w[idx] = d_WxT[(size_t)c0 * A_ + idx];
        }
        __syncthreads();
        #pragma unroll 8
        for (int cc = 0; cc < 32; cc++) {
            float4 xa  = *(const float4*)&s_x[cc * 64 + tx * 8];
            float4 xb4 = *(const float4*)&s_x[cc * 64 + tx * 8 + 4];
            float4 wa  = *(const float4*)&s_w[cc * 256 + ty * 8];
            float4 wb  = *(const float4*)&s_w[cc * 256 + ty * 8 + 4];
            float xv[8] = {xa.x, xa.y, xa.z, xa.w, xb4.x, xb4.y, xb4.z, xb4.w};
            float wv[8] = {wa.x, wa.y, wa.z, wa.w, wb.x, wb.y, wb.z, wb.w};
            #pragma unroll
            for (int i = 0; i < 8; i++)
                #pragma unroll
                for (int j = 0; j < 8; j++)
                    acc[i][j] += xv[i] * wv[j];
        }
    }

    // epilogue: relu(acc + gg + bx) . Wf, partial per thread
    float p[8];
    #pragma unroll
    for (int i = 0; i < 8; i++) {
        float s = 0.f;
        #pragma unroll
        for (int j = 0; j < 8; j++) {
            int a = ty * 8 + j;
            float v = acc[i][j] + s_gb[a];
            s += fmaxf(v, 0.f) * s_wf[a];
        }
        p[i] = s;
    }
    __syncthreads();                         // done reading s_x as tile
    #pragma unroll
    for (int i = 0; i < 8; i++)
        s_x[(tx * 8 + i) * 33 + ty] = p[i];  // red[n_local][ty], padded
    __syncthreads();
    if (tid < 64) {
        float s = 0.f;
        #pragma unroll
        for (int k = 0; k < 32; k++) s += s_x[tid * 33 + k];
        d_attraw[b * HW + n0 + tid] = s + bf[0];
    }
}

// ---------------- K3: per-batch min & sum ----------------------------
__global__ void k_reduce() {
    int b = blockIdx.x, tid = threadIdx.x;
    float mn = 3.4e38f, sm = 0.f;
    for (int n = tid; n < HW; n += 256) {
        float v = d_attraw[b * HW + n];
        mn = fminf(mn, v);
        sm += v;
    }
    #pragma unroll
    for (int o = 16; o; o >>= 1) {
        mn = fminf(mn, __shfl_down_sync(0xffffffffu, mn, o));
        sm += __shfl_down_sync(0xffffffffu, sm, o);
    }
    __shared__ float smn[8], ssm[8];
    int warp = tid >> 5, lane = tid & 31;
    if (!lane) { smn[warp] = mn; ssm[warp] = sm; }
    __syncthreads();
    if (tid == 0) {
        float m = smn[0], s = ssm[0];
        #pragma unroll
        for (int k = 1; k < 8; k++) { m = fminf(m, smn[k]); s += ssm[k]; }
        d_bmin[b] = m;
        d_bsum[b] = s;
    }
}

// ---------------- K4: normalize att, write att output region ---------
__global__ void k_att(float* __restrict__ out) {
    int b = blockIdx.x, tid = threadIdx.x;
    float mn = d_bmin[b];
    float inv = 1.f / (d_bsum[b] - (float)HW * mn);
    float* ap = out + B_ * CIN + (size_t)b * HW;
    for (int n = tid; n < HW; n += 256)
        ap[n] = (d_attraw[b * HW + n] - mn) * inv;
}

// ---------------- K5: weighted pooling out[b][c] ---------------------
__global__ __launch_bounds__(256) void k_pool(const float* __restrict__ x,
                                              float* __restrict__ out) {
    __shared__ float s_att[HW];
    __shared__ float s_red[8];
    int b = blockIdx.y, c0 = blockIdx.x * 8;
    int tid = threadIdx.x;
    const float* attp = out + B_ * CIN + (size_t)b * HW;
    for (int n = tid; n < HW; n += 256) s_att[n] = attp[n];
    __syncthreads();
    int warp = tid >> 5, lane = tid & 31;
    for (int cc = 0; cc < 8; cc++) {
        const float* xp = x + ((size_t)b * CIN + c0 + cc) * HW;
        float s = 0.f;
        for (int n = tid; n < HW; n += 256) s += xp[n] * s_att[n];
        #pragma unroll
        for (int o = 16; o; o >>= 1) s += __shfl_down_sync(0xffffffffu, s, o);
        if (!lane) s_red[warp] = s;
        __syncthreads();
        if (tid == 0) {
            float t = 0.f;
            #pragma unroll
            for (int k = 0; k < 8; k++) t += s_red[k];
            out[b * CIN + c0 + cc] = t;
        }
        __syncthreads();
    }
}

// ---------------- launch -----------------------------------------------
extern "C" void kernel_launch(void* const* d_in, const int* in_sizes, int n_in,
                              void* d_out, int out_size) {
    const float* x  = (const float*)d_in[0];   // [32,256,64,64]
    const float* g  = (const float*)d_in[1];   // [32,512]
    const float* Wg = (const float*)d_in[2];   // [256,512]
    const float* bg = (const float*)d_in[3];   // [256]
    const float* Wx = (const float*)d_in[4];   // [256,256]
    const float* bx = (const float*)d_in[5];   // [256]
    const float* Wf = (const float*)d_in[6];   // [1,256]
    const float* bf = (const float*)d_in[7];   // [1]
    float* out = (float*)d_out;                // [32*256] out ++ [32*4096] att

    k_transpose<<<dim3(8, 8), dim3(32, 8)>>>(Wx);
    k_gg<<<B_, 256>>>(g, Wg, bg);
    k_main<<<dim3(HW / 64, B_), 256>>>(x, bx, Wf, bf);
    k_reduce<<<B_, 256>>>();
    k_att<<<B_, 256>>>(out);
    k_pool<<<dim3(CIN / 8, B_), 256>>>(x, out);
}

// round 2
// speedup vs baseline: 2.1189x; 2.1189x over previous
#include <cuda_runtime.h>
#include <math.h>

#define B_   32
#define CIN  256
#define COUT 512
#define A_   256
#define HW   4096

#define KC   16            // K chunk
#define XSTR 136           // x_s row stride (words): 136%32==8 -> conflict-free frags
#define WSTR 264           // w_s row stride (words): 264%32==8

// ---- scratch ----
__device__ float d_WxT[CIN * A_];     // Wx transposed + tf32-rounded: [c][a]
__device__ float d_gg[B_ * A_];       // g @ Wg^T + bg
__device__ float d_attraw[B_ * HW];   // pre-normalization scores

__device__ __forceinline__ unsigned f2tf32(float f) {
    unsigned u;
    asm("cvt.rna.tf32.f32 %0, %1;" : "=r"(u) : "f"(f));
    return u;
}

#define MMA_TF32(c, a, bb)                                                      \
    asm volatile("mma.sync.aligned.m16n8k8.row.col.f32.tf32.tf32.f32 "          \
                 "{%0,%1,%2,%3},{%4,%5,%6,%7},{%8,%9},{%0,%1,%2,%3};"           \
                 : "+f"(c[0]), "+f"(c[1]), "+f"(c[2]), "+f"(c[3])               \
                 : "r"(a[0]), "r"(a[1]), "r"(a[2]), "r"(a[3]),                  \
                   "r"(bb[0]), "r"(bb[1]))

// ============ K0: fused [transpose Wx -> tf32 WxT] + [gg GEMV] ============
__global__ void k_pre(const float* __restrict__ Wx,
                      const float* __restrict__ g,
                      const float* __restrict__ Wg,
                      const float* __restrict__ bg) {
    if (blockIdx.x < 64) {
        // transpose: 8x8 grid of 32x32 tiles
        __shared__ float t[32][33];
        int cblk = (blockIdx.x & 7) * 32, ablk = (blockIdx.x >> 3) * 32;
        int tx = threadIdx.x & 31, ty = threadIdx.x >> 5;   // 32 x 8
        #pragma unroll
        for (int i = 0; i < 32; i += 8)
            t[ty + i][tx] = Wx[(size_t)(ablk + ty + i) * CIN + cblk + tx];
        __syncthreads();
        #pragma unroll
        for (int i = 0; i < 32; i += 8)
            d_WxT[(size_t)(cblk + ty + i) * A_ + ablk + tx] =
                __uint_as_float(f2tf32(t[tx][ty + i]));
    } else {
        // gg[b][a]
        __shared__ float gs[COUT];
        int b = blockIdx.x - 64, tid = threadIdx.x;
        gs[tid]       = g[b * COUT + tid];
        gs[tid + 256] = g[b * COUT + tid + 256];
        __syncthreads();
        int warp = tid >> 5, lane = tid & 31;
        for (int a = warp; a < A_; a += 8) {
            float s = 0.f;
            for (int k = lane; k < COUT; k += 32)
                s += gs[k] * Wg[(size_t)a * COUT + k];
            #pragma unroll
            for (int o = 16; o; o >>= 1) s += __shfl_down_sync(0xffffffffu, s, o);
            if (!lane) d_gg[b * A_ + a] = s + bg[a];
        }
    }
}

// ============ K1: main fused tf32 tensor-core GEMM + relu + Wf dot ============
// block: (n-tile of 128, batch). 8 warps as 2(n) x 4(a); warp tile 64n x 64a.
__global__ __launch_bounds__(256, 1) void k_main(
        const float* __restrict__ x,
        const float* __restrict__ bx,
        const float* __restrict__ Wf,
        const float* __restrict__ bf) {
    __shared__ unsigned s_x[KC * XSTR];   // [k][n]  (tf32 bits)
    __shared__ unsigned s_w[KC * WSTR];   // [k][a]  (tf32 bits)
    __shared__ float s_gb[A_];
    __shared__ float s_wf[A_];
    __shared__ float s_red[128 * 5];

    int b = blockIdx.y, n0 = blockIdx.x * 128;
    int tid = threadIdx.x, lane = tid & 31, w = tid >> 5;
    int q = lane & 3, r = lane >> 2;
    int wa = w & 3, wn = w >> 2;          // a-warp (x64), n-warp (x64)

    s_gb[tid] = d_gg[b * A_ + tid] + bx[tid];
    s_wf[tid] = Wf[tid];

    float acc[4][8][4];
    #pragma unroll
    for (int m = 0; m < 4; m++)
        #pragma unroll
        for (int j = 0; j < 8; j++)
            #pragma unroll
            for (int k = 0; k < 4; k++) acc[m][j][k] = 0.f;

    const float* xb = x + (size_t)b * CIN * HW + n0;
    const unsigned* wxt = (const unsigned*)d_WxT;

    float   xreg[8];     // 16 rows x 128 n / 256 thr
    unsigned wreg[16];   // 16 rows x 256 a / 256 thr

    // preload chunk 0
    #pragma unroll
    for (int t = 0; t < 8; t++) {
        int idx = tid + t * 256;
        xreg[t] = xb[(size_t)(idx >> 7) * HW + (idx & 127)];
    }
    #pragma unroll
    for (int t = 0; t < 16; t++)
        wreg[t] = wxt[tid + t * 256];

    for (int c0 = 0; c0 < CIN; c0 += KC) {
        __syncthreads();
        #pragma unroll
        for (int t = 0; t < 8; t++) {
            int idx = tid + t * 256;
            s_x[(idx >> 7) * XSTR + (idx & 127)] = f2tf32(xreg[t]);
        }
        #pragma unroll
        for (int t = 0; t < 16; t++) {
            int idx = tid + t * 256;
            s_w[(idx >> 8) * WSTR + (idx & 255)] = wreg[t];
        }
        __syncthreads();
        if (c0 + KC < CIN) {
            #pragma unroll
            for (int t = 0; t < 8; t++) {
                int idx = tid + t * 256;
                xreg[t] = xb[(size_t)(c0 + KC + (idx >> 7)) * HW + (idx & 127)];
            }
            #pragma unroll
            for (int t = 0; t < 16; t++)
                wreg[t] = wxt[(c0 + KC) * A_ + tid + t * 256];
        }
        #pragma unroll
        for (int ks = 0; ks < KC / 8; ks++) {
            int kb = ks * 8;
            unsigned af[4][4], bfr[8][2];
            #pragma unroll
            for (int m = 0; m < 4; m++) {
                int nb = wn * 64 + m * 16 + r;
                af[m][0] = s_x[(kb + q) * XSTR + nb];
                af[m][1] = s_x[(kb + q) * XSTR + nb + 8];
                af[m][2] = s_x[(kb + q + 4) * XSTR + nb];
                af[m][3] = s_x[(kb + q + 4) * XSTR + nb + 8];
            }
            #pragma unroll
            for (int j = 0; j < 8; j++) {
                int ab = wa * 64 + j * 8 + r;
                bfr[j][0] = s_w[(kb + q) * WSTR + ab];
                bfr[j][1] = s_w[(kb + q + 4) * WSTR + ab];
            }
            #pragma unroll
            for (int m = 0; m < 4; m++)
                #pragma unroll
                for (int j = 0; j < 8; j++)
                    MMA_TF32(acc[m][j], af[m], bfr[j]);
        }
    }

    // epilogue: relu(acc + gg + bx) . Wf
    #pragma unroll
    for (int m = 0; m < 4; m++) {
        #pragma unroll
        for (int h = 0; h < 2; h++) {
            float s = 0.f;
            #pragma unroll
            for (int j = 0; j < 8; j++) {
                int a0 = wa * 64 + j * 8 + 2 * q;
                float v0 = acc[m][j][2 * h]     + s_gb[a0];
                float v1 = acc[m][j][2 * h + 1] + s_gb[a0 + 1];
                s += fmaxf(v0, 0.f) * s_wf[a0];
                s += fmaxf(v1, 0.f) * s_wf[a0 + 1];
            }
            s += __shfl_xor_sync(0xffffffffu, s, 1);
            s += __shfl_xor_sync(0xffffffffu, s, 2);
            if (q == 0)
                s_red[(wn * 64 + m * 16 + h * 8 + r) * 5 + wa] = s;
        }
    }
    __syncthreads();
    if (tid < 128) {
        float s = s_red[tid * 5] + s_red[tid * 5 + 1] +
                  s_red[tid * 5 + 2] + s_red[tid * 5 + 3] + bf[0];
        d_attraw[b * HW + n0 + tid] = s;
    }
}

// ============ K2: per-batch min/sum + normalize + write att ============
__global__ void k_norm(float* __restrict__ out) {
    int b = blockIdx.x, tid = threadIdx.x;
    __shared__ float smn[8], ssm[8], fin[2];
    float mn = 3.4e38f, sm = 0.f;
    for (int n = tid; n < HW; n += 256) {
        float v = d_attraw[b * HW + n];
        mn = fminf(mn, v);
        sm += v;
    }
    #pragma unroll
    for (int o = 16; o; o >>= 1) {
        mn = fminf(mn, __shfl_down_sync(0xffffffffu, mn, o));
        sm += __shfl_down_sync(0xffffffffu, sm, o);
    }
    int warp = tid >> 5, lane = tid & 31;
    if (!lane) { smn[warp] = mn; ssm[warp] = sm; }
    __syncthreads();
    if (tid == 0) {
        float m = smn[0], s = ssm[0];
        #pragma unroll
        for (int k = 1; k < 8; k++) { m = fminf(m, smn[k]); s += ssm[k]; }
        fin[0] = m;
        fin[1] = 1.f / (s - (float)HW * m);
    }
    __syncthreads();
    float m = fin[0], inv = fin[1];
    float* ap = out + B_ * CIN + (size_t)b * HW;
    for (int n = tid; n < HW; n += 256)
        ap[n] = (d_attraw[b * HW + n] - m) * inv;
}

// ============ K3: weighted pooling out[b][c] = sum_n x*att ============
// block: (c-tile of 16, batch); warp per 2 channels; float4 loads.
__global__ __launch_bounds__(256) void k_pool(const float* __restrict__ x,
                                              float* __restrict__ out) {
    __shared__ float4 s_att[HW / 4];
    int b = blockIdx.y, c0 = blockIdx.x * 16;
    int tid = threadIdx.x, lane = tid & 31, w = tid >> 5;
    const float4* ap = (const float4*)(out + B_ * CIN + (size_t)b * HW);
    #pragma unroll
    for (int t = 0; t < 4; t++) s_att[tid + t * 256] = ap[tid + t * 256];
    __syncthreads();
    #pragma unroll
    for (int cc = 0; cc < 2; cc++) {
        int c = c0 + w * 2 + cc;
        const float4* xp = (const float4*)(x + ((size_t)b * CIN + c) * HW);
        float s = 0.f;
        #pragma unroll 4
        for (int n4 = lane; n4 < HW / 4; n4 += 32) {
            float4 xv = xp[n4];
            float4 av = s_att[n4];
            s += xv.x * av.x + xv.y * av.y + xv.z * av.z + xv.w * av.w;
        }
        #pragma unroll
        for (int o = 16; o; o >>= 1) s += __shfl_down_sync(0xffffffffu, s, o);
        if (!lane) out[b * CIN + c] = s;
    }
}

// ============ launch ============
extern "C" void kernel_launch(void* const* d_in, const int* in_sizes, int n_in,
                              void* d_out, int out_size) {
    const float* x  = (const float*)d_in[0];
    const float* g  = (const float*)d_in[1];
    const float* Wg = (const float*)d_in[2];
    const float* bg = (const float*)d_in[3];
    const float* Wx = (const float*)d_in[4];
    const float* bx = (const float*)d_in[5];
    const float* Wf = (const float*)d_in[6];
    const float* bf = (const float*)d_in[7];
    float* out = (float*)d_out;   // [32*256] out ++ [32*4096] att

    k_pre <<<96, 256>>>(Wx, g, Wg, bg);
    k_main<<<dim3(HW / 128, B_), 256>>>(x, bx, Wf, bf);
    k_norm<<<B_, 256>>>(out);
    k_pool<<<dim3(CIN / 16, B_), 256>>>(x, out);
}

// round 3
// speedup vs baseline: 2.8489x; 1.3445x over previous
#include <cuda_runtime.h>
#include <cuda_fp16.h>
#include <math.h>

#define B_   32
#define CIN  256
#define COUT 512
#define A_   256
#define HW   4096

#define NT   128          // n-positions per CTA
#define C2   (CIN/2)      // packed-k rows (half2 along c)
#define XSTR 136          // s_x row stride in words (136%32==8 -> conflict-free frags)
#define WSTR 264          // s_w row stride in words
#define SW_OFF 0
#define SX_OFF (C2*WSTR)              // 33792
#define DYN_WORDS (SX_OFF + C2*XSTR) // 51200 words = 204800 B

// ---- scratch ----
__device__ unsigned d_Wp[C2 * A_];        // packed half2 {Wx[a][2c2],Wx[a][2c2+1]} at [c2][a]
__device__ float d_gg[B_ * A_];           // g @ Wg^T + bg
__device__ float d_attraw[B_ * HW];       // pre-normalization scores
__device__ float d_Pp[B_ * 32 * CIN];     // pooling partials  sum_n x*attraw
__device__ float d_Sp[B_ * 32 * CIN];     // pooling partials  sum_n x
__device__ float d_mnp[B_ * 32];          // per-tile min of attraw
__device__ float d_smp[B_ * 32];          // per-tile sum of attraw

#define MMA_F16(c, a, bb)                                                       \
    asm volatile("mma.sync.aligned.m16n8k16.row.col.f32.f16.f16.f32 "           \
                 "{%0,%1,%2,%3},{%4,%5,%6,%7},{%8,%9},{%0,%1,%2,%3};"           \
                 : "+f"(c[0]), "+f"(c[1]), "+f"(c[2]), "+f"(c[3])               \
                 : "r"(a[0]), "r"(a[1]), "r"(a[2]), "r"(a[3]),                  \
                   "r"(bb[0]), "r"(bb[1]))

__device__ __forceinline__ unsigned pack_h2(float lo, float hi) {
    __half2 h = __floats2half2_rn(lo, hi);
    return *(unsigned*)&h;
}

// ============ K0: [transpose+pack Wx] (blocks 0-31) + [gg GEMV] (32-63) ======
__global__ void k_pre(const float* __restrict__ Wx,
                      const float* __restrict__ g,
                      const float* __restrict__ Wg,
                      const float* __restrict__ bg) {
    if (blockIdx.x < 32) {
        // tile: 32 a-rows x 64 c-cols -> d_Wp words [32 c2][32 a]
        __shared__ float t[32][65];
        int cb = (blockIdx.x & 3) * 64, ab = (blockIdx.x >> 2) * 32;
        int tid = threadIdx.x;
        #pragma unroll
        for (int u = 0; u < 8; u++) {
            int idx = tid + u * 256;            // 2048 = 32*64
            int i = idx >> 6, j = idx & 63;
            t[i][j] = Wx[(size_t)(ab + i) * CIN + cb + j];
        }
        __syncthreads();
        #pragma unroll
        for (int u = 0; u < 4; u++) {
            int idx = tid + u * 256;            // 1024 = 32 c2 * 32 a
            int jj = idx >> 5, i = idx & 31;
            d_Wp[(size_t)(cb / 2 + jj) * A_ + ab + i] = pack_h2(t[i][2 * jj], t[i][2 * jj + 1]);
        }
    } else {
        __shared__ float gs[COUT];
        int b = blockIdx.x - 32, tid = threadIdx.x;
        gs[tid]       = g[b * COUT + tid];
        gs[tid + 256] = g[b * COUT + tid + 256];
        __syncthreads();
        int warp = tid >> 5, lane = tid & 31;
        for (int a = warp; a < A_; a += 8) {
            float s = 0.f;
            for (int k = lane; k < COUT; k += 32)
                s += gs[k] * Wg[(size_t)a * COUT + k];
            #pragma unroll
            for (int o = 16; o; o >>= 1) s += __shfl_down_sync(0xffffffffu, s, o);
            if (!lane) d_gg[b * A_ + a] = s + bg[a];
        }
    }
}

// ============ K1: fp16 tensor GEMM + relu.Wf + tile stats + pool partials ====
// CTA = (n-tile of 128, batch). 8 warps as 2(n) x 4(a), warp tile 64n x 64a.
__global__ __launch_bounds__(256, 1) void k_main(
        const float* __restrict__ x,
        const float* __restrict__ bx,
        const float* __restrict__ Wf,
        const float* __restrict__ bf) {
    extern __shared__ unsigned smem[];
    unsigned* SW = smem + SW_OFF;     // [c2][a]  half2 words
    unsigned* SX = smem + SX_OFF;     // [c2][n]  half2 words
    __shared__ float s_gb[A_];
    __shared__ float s_wf[A_];
    __shared__ float s_red[NT * 5];
    __shared__ float s_att[NT];

    int b = blockIdx.y, nt = blockIdx.x, n0 = nt * NT;
    int tid = threadIdx.x, lane = tid & 31, w = tid >> 5;
    int t = lane & 3, gq = lane >> 2;
    int wa = w & 3, wn = w >> 2;

    s_gb[tid] = d_gg[b * A_ + tid] + bx[tid];
    s_wf[tid] = Wf[tid];

    const float* xb = x + (size_t)b * CIN * HW + n0;

    // ---- load full W [128 c2][256 a] from packed global ----
    {
        const uint4* wp = (const uint4*)d_Wp;
        #pragma unroll
        for (int u = 0; u < 32; u++) {
            int v = tid + u * 256;            // 8192 uint4
            int c2 = v >> 6, a4 = (v & 63) * 4;
            uint4 r = wp[v];
            *(uint4*)&SW[c2 * WSTR + a4] = r;
        }
    }
    // ---- load full x tile [128 c2][128 n], cvt f32->f16 pairs ----
    {
        #pragma unroll
        for (int u = 0; u < 16; u++) {
            int v = tid + u * 256;            // 4096 uint4-groups
            int c2 = v >> 5, n4 = (v & 31) * 4;
            const float4 r0 = *(const float4*)&xb[(size_t)(2 * c2) * HW + n4];
            const float4 r1 = *(const float4*)&xb[(size_t)(2 * c2 + 1) * HW + n4];
            uint4 o;
            o.x = pack_h2(r0.x, r1.x);
            o.y = pack_h2(r0.y, r1.y);
            o.z = pack_h2(r0.z, r1.z);
            o.w = pack_h2(r0.w, r1.w);
            *(uint4*)&SX[c2 * XSTR + n4] = o;
        }
    }
    __syncthreads();

    // ---- MMA mainloop: full K, 16 ksteps of k=16 ----
    float acc[4][8][4];
    #pragma unroll
    for (int m = 0; m < 4; m++)
        #pragma unroll
        for (int j = 0; j < 8; j++)
            #pragma unroll
            for (int k = 0; k < 4; k++) acc[m][j][k] = 0.f;

    for (int ks = 0; ks < 16; ks++) {
        int kb = ks * 8;                      // c2-row base
        unsigned af[4][4], bfr[8][2];
        #pragma unroll
        for (int m = 0; m < 4; m++) {
            int nb = wn * 64 + m * 16 + gq;
            af[m][0] = SX[(kb + t) * XSTR + nb];
            af[m][1] = SX[(kb + t) * XSTR + nb + 8];
            af[m][2] = SX[(kb + t + 4) * XSTR + nb];
            af[m][3] = SX[(kb + t + 4) * XSTR + nb + 8];
        }
        #pragma unroll
        for (int j = 0; j < 8; j++) {
            int ab = wa * 64 + j * 8 + gq;
            bfr[j][0] = SW[(kb + t) * WSTR + ab];
            bfr[j][1] = SW[(kb + t + 4) * WSTR + ab];
        }
        #pragma unroll
        for (int m = 0; m < 4; m++)
            #pragma unroll
            for (int j = 0; j < 8; j++)
                MMA_F16(acc[m][j], af[m], bfr[j]);
    }

    // ---- epilogue 1: relu(acc + gg + bx) . Wf ----
    #pragma unroll
    for (int m = 0; m < 4; m++) {
        #pragma unroll
        for (int h = 0; h < 2; h++) {
            float s = 0.f;
            #pragma unroll
            for (int j = 0; j < 8; j++) {
                int a0 = wa * 64 + j * 8 + 2 * t;
                float v0 = acc[m][j][2 * h]     + s_gb[a0];
                float v1 = acc[m][j][2 * h + 1] + s_gb[a0 + 1];
                s += fmaxf(v0, 0.f) * s_wf[a0];
                s += fmaxf(v1, 0.f) * s_wf[a0 + 1];
            }
            s += __shfl_xor_sync(0xffffffffu, s, 1);
            s += __shfl_xor_sync(0xffffffffu, s, 2);
            if (t == 0)
                s_red[(wn * 64 + m * 16 + h * 8 + gq) * 5 + wa] = s;
        }
    }
    __syncthreads();
    if (tid < NT) {
        float s = s_red[tid * 5] + s_red[tid * 5 + 1] +
                  s_red[tid * 5 + 2] + s_red[tid * 5 + 3] + bf[0];
        s_att[tid] = s;
        d_attraw[b * HW + n0 + tid] = s;
    }
    __syncthreads();

    // ---- epilogue 2: tile min & sum of attraw (warp 0) ----
    if (w == 0) {
        float mn = 3.4e38f, sm = 0.f;
        #pragma unroll
        for (int k = 0; k < 4; k++) {
            float v = s_att[lane + 32 * k];
            mn = fminf(mn, v);
            sm += v;
        }
        #pragma unroll
        for (int o = 16; o; o >>= 1) {
            mn = fminf(mn, __shfl_down_sync(0xffffffffu, mn, o));
            sm += __shfl_down_sync(0xffffffffu, sm, o);
        }
        if (!lane) { d_mnp[b * 32 + nt] = mn; d_smp[b * 32 + nt] = sm; }
    }

    // ---- epilogue 3: pooling partials from resident x tile ----
    {
        int c = tid, c2 = c >> 1, hi = c & 1;
        float p = 0.f, s = 0.f;
        #pragma unroll 8
        for (int n = 0; n < NT; n++) {
            __half2 h = *(__half2*)&SX[c2 * XSTR + n];
            float v = hi ? __high2float(h) : __low2float(h);
            p = fmaf(v, s_att[n], p);
            s += v;
        }
        d_Pp[((size_t)b * 32 + nt) * CIN + c] = p;
        d_Sp[((size_t)b * 32 + nt) * CIN + c] = s;
    }
}

// ============ K2: finalize — reduce stats, write att and out ============
__global__ void k_fin(float* __restrict__ out) {
    __shared__ float fin[2];
    int b = blockIdx.x, tid = threadIdx.x, lane = tid & 31;
    if (tid < 32) {
        float mn = d_mnp[b * 32 + lane];
        float sm = d_smp[b * 32 + lane];
        #pragma unroll
        for (int o = 16; o; o >>= 1) {
            mn = fminf(mn, __shfl_down_sync(0xffffffffu, mn, o));
            sm += __shfl_down_sync(0xffffffffu, sm, o);
        }
        if (!lane) {
            fin[0] = mn;
            fin[1] = 1.f / (sm - (float)HW * mn);
        }
    }
    __syncthreads();
    float mn = fin[0], inv = fin[1];

    // out[b][c] = inv * (sum_nt Pp - mn * sum_nt Sp)
    {
        int c = tid;
        float P = 0.f, S = 0.f;
        #pragma unroll
        for (int nt = 0; nt < 32; nt++) {
            P += d_Pp[((size_t)b * 32 + nt) * CIN + c];
            S += d_Sp[((size_t)b * 32 + nt) * CIN + c];
        }
        out[b * CIN + c] = (P - mn * S) * inv;
    }
    // att
    float* ap = out + B_ * CIN + (size_t)b * HW;
    for (int n = tid; n < HW; n += 256)
        ap[n] = (d_attraw[b * HW + n] - mn) * inv;
}

// ============ launch ============
extern "C" void kernel_launch(void* const* d_in, const int* in_sizes, int n_in,
                              void* d_out, int out_size) {
    const float* x  = (const float*)d_in[0];
    const float* g  = (const float*)d_in[1];
    const float* Wg = (const float*)d_in[2];
    const float* bg = (const float*)d_in[3];
    const float* Wx = (const float*)d_in[4];
    const float* bx = (const float*)d_in[5];
    const float* Wf = (const float*)d_in[6];
    const float* bf = (const float*)d_in[7];
    float* out = (float*)d_out;   // [32*256] out ++ [32*4096] att

    cudaFuncSetAttribute(k_main, cudaFuncAttributeMaxDynamicSharedMemorySize,
                         DYN_WORDS * 4);

    k_pre <<<64, 256>>>(Wx, g, Wg, bg);
    k_main<<<dim3(HW / NT, B_), 256, DYN_WORDS * 4>>>(x, bx, Wf, bf);
    k_fin <<<B_, 256>>>(out);
}

// round 5
// speedup vs baseline: 4.1063x; 1.4414x over previous
#include <cuda_runtime.h>
#include <cuda_fp16.h>
#include <math.h>

#define B_   32
#define CIN  256
#define COUT 512
#define A_   256
#define HW   4096

#define NT   128          // n-positions per CTA
#define C2   (CIN/2)      // packed-k rows (half2 along c)
#define XSTR 136          // s_x row stride in words (136%32==8 -> conflict-free frags)
#define WSTR 264          // s_w row stride in words
#define SW_OFF 0
#define SX_OFF (C2*WSTR)              // 33792
#define DYN_WORDS (SX_OFF + C2*XSTR) // 51200 words = 204800 B

// ---- scratch ----
__device__ unsigned d_Wp[C2 * A_];        // packed half2 {Wx[a][2c2],Wx[a][2c2+1]} at [c2][a]
__device__ float d_gg[B_ * A_];           // g @ Wg^T + bg
__device__ float d_attraw[B_ * HW];       // pre-normalization scores
__device__ float d_Pp[B_ * 32 * CIN];     // pooling partials  sum_n x*attraw
__device__ float d_Sp[B_ * 32 * CIN];     // pooling partials  sum_n x
__device__ float d_mnp[B_ * 32];          // per-tile min of attraw
__device__ float d_smp[B_ * 32];          // per-tile sum of attraw

#define MMA_F16(c, a, bb)                                                       \
    asm volatile("mma.sync.aligned.m16n8k16.row.col.f32.f16.f16.f32 "           \
                 "{%0,%1,%2,%3},{%4,%5,%6,%7},{%8,%9},{%0,%1,%2,%3};"           \
                 : "+f"(c[0]), "+f"(c[1]), "+f"(c[2]), "+f"(c[3])               \
                 : "r"(a[0]), "r"(a[1]), "r"(a[2]), "r"(a[3]),                  \
                   "r"(bb[0]), "r"(bb[1]))

__device__ __forceinline__ unsigned pack_h2(float lo, float hi) {
    __half2 h = __floats2half2_rn(lo, hi);
    return *(unsigned*)&h;
}

// ============ K0: [transpose+pack Wx] (blocks 0-31) + [gg GEMV] (32-287) =====
__global__ void k_pre(const float* __restrict__ Wx,
                      const float* __restrict__ g,
                      const float* __restrict__ Wg,
                      const float* __restrict__ bg) {
    if (blockIdx.x < 32) {
        // tile: 32 a-rows x 64 c-cols -> d_Wp words [32 c2][32 a]
        __shared__ float t[32][65];
        int cb = (blockIdx.x & 3) * 64, ab = (blockIdx.x >> 2) * 32;
        int tid = threadIdx.x;
        #pragma unroll
        for (int u = 0; u < 8; u++) {
            int idx = tid + u * 256;            // 2048 = 32*64
            int i = idx >> 6, j = idx & 63;
            t[i][j] = Wx[(size_t)(ab + i) * CIN + cb + j];
        }
        __syncthreads();
        #pragma unroll
        for (int u = 0; u < 4; u++) {
            int idx = tid + u * 256;            // 1024 = 32 c2 * 32 a
            int jj = idx >> 5, i = idx & 31;
            d_Wp[(size_t)(cb / 2 + jj) * A_ + ab + i] = pack_h2(t[i][2 * jj], t[i][2 * jj + 1]);
        }
    } else {
        // gg: one block per (b, 32-a group); one warp per output a
        __shared__ float gs[COUT];
        int idx = blockIdx.x - 32;              // 0..255
        int b = idx >> 3, a0 = (idx & 7) * 32;
        int tid = threadIdx.x;
        gs[tid]       = g[b * COUT + tid];
        gs[tid + 256] = g[b * COUT + tid + 256];
        __syncthreads();
        int warp = tid >> 5, lane = tid & 31;
        #pragma unroll
        for (int i = 0; i < 4; i++) {
            int a = a0 + warp * 4 + i;
            float s = 0.f;
            #pragma unroll
            for (int k = lane; k < COUT; k += 32)
                s += gs[k] * Wg[(size_t)a * COUT + k];
            #pragma unroll
            for (int o = 16; o; o >>= 1) s += __shfl_down_sync(0xffffffffu, s, o);
            if (!lane) d_gg[b * A_ + a] = s + bg[a];
        }
    }
}

// ============ K1: fp16 tensor GEMM + relu.Wf + tile stats + pool partials ====
// CTA = (n-tile of 128, batch). 8 warps as 2(n) x 4(a), warp tile 64n x 64a.
__global__ __launch_bounds__(256, 1) void k_main(
        const float* __restrict__ x,
        const float* __restrict__ bx,
        const float* __restrict__ Wf,
        const float* __restrict__ bf) {
    extern __shared__ unsigned smem[];
    unsigned* SW = smem + SW_OFF;     // [c2][a]  half2 words
    unsigned* SX = smem + SX_OFF;     // [c2][n]  half2 words
    __shared__ float s_gb[A_];
    __shared__ float s_wf[A_];
    __shared__ float s_red[NT * 5];
    __shared__ float s_att[NT];

    int b = blockIdx.y, nt = blockIdx.x, n0 = nt * NT;
    int tid = threadIdx.x, lane = tid & 31, w = tid >> 5;
    int t = lane & 3, gq = lane >> 2;
    int wa = w & 3, wn = w >> 2;

    const float* xb = x + (size_t)b * CIN * HW + n0;

    // ---- W tile [128 c2][256 a] via cp.async (overlaps x conversion below) ----
    {
        const uint4* wp = (const uint4*)d_Wp;
        #pragma unroll
        for (int u = 0; u < 32; u++) {
            int v = tid + u * 256;            // 8192 uint4
            int c2 = v >> 6, a4 = (v & 63) * 4;
            unsigned daddr = (unsigned)__cvta_generic_to_shared(&SW[c2 * WSTR + a4]);
            asm volatile("cp.async.cg.shared.global [%0], [%1], 16;\n"
                         :: "r"(daddr), "l"(wp + v));
        }
        asm volatile("cp.async.commit_group;\n");
    }

    s_gb[tid] = d_gg[b * A_ + tid] + bx[tid];
    s_wf[tid] = Wf[tid];

    // ---- load full x tile [128 c2][128 n], cvt f32->f16 pairs ----
    {
        #pragma unroll
        for (int u = 0; u < 16; u++) {
            int v = tid + u * 256;            // 4096 uint4-groups
            int c2 = v >> 5, n4 = (v & 31) * 4;
            const float4 r0 = *(const float4*)&xb[(size_t)(2 * c2) * HW + n4];
            const float4 r1 = *(const float4*)&xb[(size_t)(2 * c2 + 1) * HW + n4];
            uint4 o;
            o.x = pack_h2(r0.x, r1.x);
            o.y = pack_h2(r0.y, r1.y);
            o.z = pack_h2(r0.z, r1.z);
            o.w = pack_h2(r0.w, r1.w);
            *(uint4*)&SX[c2 * XSTR + n4] = o;
        }
    }
    asm volatile("cp.async.wait_group 0;\n");
    __syncthreads();

    // ---- MMA mainloop: full K, 16 ksteps of k=16 ----
    float acc[4][8][4];
    #pragma unroll
    for (int m = 0; m < 4; m++)
        #pragma unroll
        for (int j = 0; j < 8; j++)
            #pragma unroll
            for (int k = 0; k < 4; k++) acc[m][j][k] = 0.f;

    for (int ks = 0; ks < 16; ks++) {
        int kb = ks * 8;                      // c2-row base
        unsigned af[4][4], bfr[8][2];
        #pragma unroll
        for (int m = 0; m < 4; m++) {
            int nb = wn * 64 + m * 16 + gq;
            af[m][0] = SX[(kb + t) * XSTR + nb];
            af[m][1] = SX[(kb + t) * XSTR + nb + 8];
            af[m][2] = SX[(kb + t + 4) * XSTR + nb];
            af[m][3] = SX[(kb + t + 4) * XSTR + nb + 8];
        }
        #pragma unroll
        for (int j = 0; j < 8; j++) {
            int ab = wa * 64 + j * 8 + gq;
            bfr[j][0] = SW[(kb + t) * WSTR + ab];
            bfr[j][1] = SW[(kb + t + 4) * WSTR + ab];
        }
        #pragma unroll
        for (int m = 0; m < 4; m++)
            #pragma unroll
            for (int j = 0; j < 8; j++)
                MMA_F16(acc[m][j], af[m], bfr[j]);
    }

    // ---- epilogue 1: relu(acc + gg + bx) . Wf ----
    #pragma unroll
    for (int m = 0; m < 4; m++) {
        #pragma unroll
        for (int h = 0; h < 2; h++) {
            float s = 0.f;
            #pragma unroll
            for (int j = 0; j < 8; j++) {
                int a0 = wa * 64 + j * 8 + 2 * t;
                float v0 = acc[m][j][2 * h]     + s_gb[a0];
                float v1 = acc[m][j][2 * h + 1] + s_gb[a0 + 1];
                s += fmaxf(v0, 0.f) * s_wf[a0];
                s += fmaxf(v1, 0.f) * s_wf[a0 + 1];
            }
            s += __shfl_xor_sync(0xffffffffu, s, 1);
            s += __shfl_xor_sync(0xffffffffu, s, 2);
            if (t == 0)
                s_red[(wn * 64 + m * 16 + h * 8 + gq) * 5 + wa] = s;
        }
    }
    __syncthreads();
    if (tid < NT) {
        float s = s_red[tid * 5] + s_red[tid * 5 + 1] +
                  s_red[tid * 5 + 2] + s_red[tid * 5 + 3] + bf[0];
        s_att[tid] = s;
        d_attraw[b * HW + n0 + tid] = s;
    }
    __syncthreads();

    // ---- epilogue 2: tile min & sum of attraw (warp 0) ----
    if (w == 0) {
        float mn = 3.4e38f, sm = 0.f;
        #pragma unroll
        for (int k = 0; k < 4; k++) {
            float v = s_att[lane + 32 * k];
            mn = fminf(mn, v);
            sm += v;
        }
        #pragma unroll
        for (int o = 16; o; o >>= 1) {
            mn = fminf(mn, __shfl_down_sync(0xffffffffu, mn, o));
            sm += __shfl_down_sync(0xffffffffu, sm, o);
        }
        if (!lane) { d_mnp[b * 32 + nt] = mn; d_smp[b * 32 + nt] = sm; }
    }

    // ---- epilogue 3: pooling partials from resident x tile ----
    {
        int c = tid, c2 = c >> 1, hi = c & 1;
        float p = 0.f, s = 0.f;
        #pragma unroll 8
        for (int n = 0; n < NT; n++) {
            __half2 h = *(__half2*)&SX[c2 * XSTR + n];
            float v = hi ? __high2float(h) : __low2float(h);
            p = fmaf(v, s_att[n], p);
            s += v;
        }
        d_Pp[((size_t)b * 32 + nt) * CIN + c] = p;
        d_Sp[((size_t)b * 32 + nt) * CIN + c] = s;
    }
}

// ============ K2: finalize — reduce stats, write att and out ============
__global__ void k_fin(float* __restrict__ out) {
    __shared__ float fin[2];
    int b = blockIdx.x, tid = threadIdx.x, lane = tid & 31;
    if (tid < 32) {
        float mn = d_mnp[b * 32 + lane];
        float sm = d_smp[b * 32 + lane];
        #pragma unroll
        for (int o = 16; o; o >>= 1) {
            mn = fminf(mn, __shfl_down_sync(0xffffffffu, mn, o));
            sm += __shfl_down_sync(0xffffffffu, sm, o);
        }
        if (!lane) {
            fin[0] = mn;
            fin[1] = 1.f / (sm - (float)HW * mn);
        }
    }
    __syncthreads();
    float mn = fin[0], inv = fin[1];

    // out[b][c] = inv * (sum_nt Pp - mn * sum_nt Sp)
    {
        int c = tid;
        float P = 0.f, S = 0.f;
        #pragma unroll
        for (int nt = 0; nt < 32; nt++) {
            P += d_Pp[((size_t)b * 32 + nt) * CIN + c];
            S += d_Sp[((size_t)b * 32 + nt) * CIN + c];
        }
        out[b * CIN + c] = (P - mn * S) * inv;
    }
    // att
    float* ap = out + B_ * CIN + (size_t)b * HW;
    for (int n = tid; n < HW; n += 256)
        ap[n] = (d_attraw[b * HW + n] - mn) * inv;
}

// ============ launch ============
extern "C" void kernel_launch(void* const* d_in, const int* in_sizes, int n_in,
                              void* d_out, int out_size) {
    const float* x  = (const float*)d_in[0];
    const float* g  = (const float*)d_in[1];
    const float* Wg = (const float*)d_in[2];
    const float* bg = (const float*)d_in[3];
    const float* Wx = (const float*)d_in[4];
    const float* bx = (const float*)d_in[5];
    const float* Wf = (const float*)d_in[6];
    const float* bf = (const float*)d_in[7];
    float* out = (float*)d_out;   // [32*256] out ++ [32*4096] att

    cudaFuncSetAttribute(k_main, cudaFuncAttributeMaxDynamicSharedMemorySize,
                         DYN_WORDS * 4);

    k_pre <<<288, 256>>>(Wx, g, Wg, bg);
    k_main<<<dim3(HW / NT, B_), 256, DYN_WORDS * 4>>>(x, bx, Wf, bf);
    k_fin <<<B_, 256>>>(out);
}